// round 4
// baseline (speedup 1.0000x reference)
#include <cuda_runtime.h>

#define HIDDEN 32
#define FEAT 30
#define TSTEPS 512
#define BATCH 4096
#define CHUNK 16
#define N4BLK 544            /* blocks 0..543: 4 samples; 544..1183: 3 samples */
#define GRIDB 1184           /* = 148 SMs * 8 warps */
#define FULLMASK 0xffffffffu

typedef unsigned long long ull;

__device__ __forceinline__ float sigf(float x) {
    float e = __expf(-x);
    return __fdividef(1.0f, 1.0f + e);
}
__device__ __forceinline__ float tanh_fast(float x) {
    float e = __expf(-2.0f * x);
    return __fdividef(1.0f - e, 1.0f + e);
}
__device__ __forceinline__ ull fma2(ull a, ull b, ull c) {
    ull d;
    asm("fma.rn.f32x2 %0, %1, %2, %3;" : "=l"(d) : "l"(a), "l"(b), "l"(c));
    return d;
}
__device__ __forceinline__ ull pack2(float lo, float hi) {
    ull d; asm("mov.b64 %0, {%1, %2};" : "=l"(d) : "f"(lo), "f"(hi)); return d;
}
__device__ __forceinline__ ull dup2(float v) {
    ull d; asm("mov.b64 %0, {%1, %1};" : "=l"(d) : "f"(v)); return d;
}
__device__ __forceinline__ float2 unpack2(ull v) {
    float lo, hi; asm("mov.b64 {%0, %1}, %2;" : "=f"(lo), "=f"(hi) : "l"(v));
    return make_float2(lo, hi);
}

struct Smem {
    ulonglong2 sWih[FEAT][HIDDEN];   // [k][j] = ((w_i,w_f),(w_g,w_o))
    ulonglong2 xq[2][FEAT];          // [buf][k] = ((xA,xB),(xC,xD))
    ulonglong2 hq[2][HIDDEN];        // [buf][j] = ((hA,hB),(hC,hD))
    ulonglong2 hist[CHUNK][33];      // [slot][j] = ((hsA,hsB),(hsC,hsD)), padded
    ull wcd0[HIDDEN], wcd1[HIDDEN], wcdl[HIDDEN];
};

template<int NS>
__device__ __forceinline__ void run_lstm(
    Smem* sm, int s0, int lane,
    const float* __restrict__ x,
    const float* __restrict__ h0, const float* __restrict__ c0,
    const ull* whh_if, const ull* whh_go,
    ull bias_if, ull bias_go,
    float cb0, float cb1, float blv, float clv,
    float* __restrict__ pos_out, float* __restrict__ lv_out,
    float* __restrict__ hT_out, float* __restrict__ cT_out)
{
    const float* xp[NS];
    float h[NS], c[NS];
    #pragma unroll
    for (int s = 0; s < NS; ++s) {
        xp[s] = x + (size_t)(s0 + s) * TSTEPS * FEAT;
        h[s] = h0[(s0 + s) * HIDDEN + lane];
        c[s] = c0[(s0 + s) * HIDDEN + lane];
    }

    sm->hq[0][lane] = make_ulonglong2(
        pack2(h[0], h[1]),
        pack2(h[2 < NS ? 2 : 0], NS == 4 ? h[3] : 0.f));
    if (lane < FEAT) {
        sm->xq[0][lane] = make_ulonglong2(
            pack2(xp[0][lane], xp[1][lane]),
            pack2(xp[2 < NS ? 2 : 0][lane], NS == 4 ? xp[3][lane] : 0.f));
    }
    __syncwarp();

    for (int t = 0; t < TSTEPS; ++t) {
        const int bsel = t & 1;
        const int slot = t & (CHUNK - 1);

        // prefetch next x
        float xn[NS];
        const bool pf = (t + 1 < TSTEPS) && (lane < FEAT);
        #pragma unroll
        for (int s = 0; s < NS; ++s) xn[s] = pf ? xp[s][(t + 1) * FEAT + lane] : 0.f;

        const ulonglong2 mq = sm->xq[bsel][FEAT - 1];
        const float2 mab = unpack2(mq.x), mcd = unpack2(mq.y);
        const float mv[4] = {mab.x, mab.y, mcd.x, mcd.y};
        bool act[NS]; bool any = false;
        #pragma unroll
        for (int s = 0; s < NS; ++s) { act[s] = (mv[s] == 1.0f); any |= act[s]; }

        float hs[NS];
        if (any) {
            ull aif[NS], ago[NS];
            #pragma unroll
            for (int s = 0; s < NS; ++s) { aif[s] = bias_if; ago[s] = bias_go; }

            #pragma unroll
            for (int k = 0; k < FEAT; ++k) {
                const ulonglong2 xk = sm->xq[bsel][k];
                const float2 ab = unpack2(xk.x), cd = unpack2(xk.y);
                const float v[4] = {ab.x, ab.y, cd.x, cd.y};
                const ulonglong2 w = sm->sWih[k][lane];
                #pragma unroll
                for (int s = 0; s < NS; ++s) {
                    const ull vv = dup2(v[s]);
                    aif[s] = fma2(vv, w.x, aif[s]);
                    ago[s] = fma2(vv, w.y, ago[s]);
                }
            }
            #pragma unroll
            for (int k = 0; k < HIDDEN; ++k) {
                const ulonglong2 hk = sm->hq[bsel][k];
                const float2 ab = unpack2(hk.x), cd = unpack2(hk.y);
                const float v[4] = {ab.x, ab.y, cd.x, cd.y};
                const ull wi = whh_if[k], wg = whh_go[k];
                #pragma unroll
                for (int s = 0; s < NS; ++s) {
                    const ull vv = dup2(v[s]);
                    aif[s] = fma2(vv, wi, aif[s]);
                    ago[s] = fma2(vv, wg, ago[s]);
                }
            }
            #pragma unroll
            for (int s = 0; s < NS; ++s) {
                const float2 g1 = unpack2(aif[s]), g2 = unpack2(ago[s]);
                const float cn = fmaf(sigf(g1.y), c[s], sigf(g1.x) * tanh_fast(g2.x));
                const float hn = sigf(g2.y) * tanh_fast(cn);
                c[s] = act[s] ? cn : c[s];
                h[s] = act[s] ? hn : h[s];
                hs[s] = act[s] ? hn : 0.f;
            }
        } else {
            #pragma unroll
            for (int s = 0; s < NS; ++s) hs[s] = 0.f;
        }

        sm->hq[bsel ^ 1][lane] = make_ulonglong2(
            pack2(h[0], h[1]),
            pack2(h[2 < NS ? 2 : 0], NS == 4 ? h[3] : 0.f));
        sm->hist[slot][lane] = make_ulonglong2(
            pack2(hs[0], hs[1]),
            pack2(hs[2 < NS ? 2 : 0], NS == 4 ? hs[3] : 0.f));
        if (pf) {
            sm->xq[bsel ^ 1][lane] = make_ulonglong2(
                pack2(xn[0], xn[1]),
                pack2(xn[2 < NS ? 2 : 0], NS == 4 ? xn[3] : 0.f));
        }
        __syncwarp();

        // bulk head phase over the finished 16-step chunk
        if (slot == CHUNK - 1) {
            const int tt = lane & 15;
            const int pr = lane >> 4;
            const ull* hrow = reinterpret_cast<const ull*>(&sm->hist[tt][0]) + pr;
            ull p0 = 0ULL, p1 = 0ULL, pl = 0ULL;
            #pragma unroll
            for (int j = 0; j < HIDDEN; ++j) {
                const ull hv = hrow[j * 2];
                p0 = fma2(hv, sm->wcd0[j], p0);
                p1 = fma2(hv, sm->wcd1[j], p1);
                pl = fma2(hv, sm->wcdl[j], pl);
            }
            const float2 q0 = unpack2(p0), q1 = unpack2(p1), ql = unpack2(pl);
            const int tg = t - (CHUNK - 1) + tt;
            const size_t oA = (size_t)(s0 + pr * 2) * TSTEPS + tg;
            const size_t oB = oA + TSTEPS;
            reinterpret_cast<float2*>(pos_out)[oA] = make_float2(q0.x + cb0, q1.x + cb1);
            lv_out[oA] = sigf(ql.x + blv);
            if (NS == 4 || pr == 0) {
                reinterpret_cast<float2*>(pos_out)[oB] = make_float2(q0.y + cb0, q1.y + cb1);
                lv_out[oB] = sigf(ql.y + blv);
            }
            __syncwarp();
        }
    }

    #pragma unroll
    for (int s = 0; s < NS; ++s) {
        hT_out[(s0 + s) * HIDDEN + lane] = h[s];
        cT_out[(s0 + s) * HIDDEN + lane] = c[s];
    }
}

__global__ void __launch_bounds__(32)
lstm_fused_kernel(
    const float* __restrict__ x, const float* __restrict__ h0, const float* __restrict__ c0,
    const float* __restrict__ W_ih, const float* __restrict__ W_hh,
    const float* __restrict__ b_ih, const float* __restrict__ b_hh,
    const float* __restrict__ W_all, const float* __restrict__ b_all,
    const float* __restrict__ W_pos, const float* __restrict__ b_pos,
    const float* __restrict__ W_lv, const float* __restrict__ b_lv,
    float* __restrict__ out)
{
    __shared__ Smem sm;
    const int lane = threadIdx.x;

    #pragma unroll
    for (int k = 0; k < FEAT; ++k) {
        sm.sWih[k][lane] = make_ulonglong2(
            pack2(W_ih[lane * FEAT + k],        W_ih[(32 + lane) * FEAT + k]),
            pack2(W_ih[(64 + lane) * FEAT + k], W_ih[(96 + lane) * FEAT + k]));
    }
    ull whh_if[HIDDEN], whh_go[HIDDEN];
    #pragma unroll
    for (int k = 0; k < HIDDEN; ++k) {
        whh_if[k] = pack2(W_hh[lane * HIDDEN + k],        W_hh[(32 + lane) * HIDDEN + k]);
        whh_go[k] = pack2(W_hh[(64 + lane) * HIDDEN + k], W_hh[(96 + lane) * HIDDEN + k]);
    }
    // folded heads: wc = W_pos @ W_all, cb = W_pos @ b_all + b_pos
    float wc0 = 0.f, wc1 = 0.f, cb0 = b_pos[0], cb1 = b_pos[1];
    #pragma unroll
    for (int m = 0; m < HIDDEN; ++m) {
        const float wa = W_all[m * HIDDEN + lane];
        wc0 = fmaf(W_pos[m],      wa, wc0);
        wc1 = fmaf(W_pos[32 + m], wa, wc1);
        cb0 = fmaf(W_pos[m],      b_all[m], cb0);
        cb1 = fmaf(W_pos[32 + m], b_all[m], cb1);
    }
    sm.wcd0[lane] = dup2(wc0);
    sm.wcd1[lane] = dup2(wc1);
    sm.wcdl[lane] = dup2(W_lv[lane]);
    const float blv = b_lv[0];
    const float clv = sigf(blv);

    const ull bias_if = pack2(b_ih[lane]      + b_hh[lane],
                              b_ih[32 + lane] + b_hh[32 + lane]);
    const ull bias_go = pack2(b_ih[64 + lane] + b_hh[64 + lane],
                              b_ih[96 + lane] + b_hh[96 + lane]);

    float* pos_out = out;
    float* lv_out  = out + (size_t)BATCH * TSTEPS * 2;
    float* hT_out  = out + (size_t)BATCH * TSTEPS * 3;
    float* cT_out  = hT_out + BATCH * HIDDEN;

    const int b = blockIdx.x;
    if (b < N4BLK) {
        run_lstm<4>(&sm, b * 4, lane, x, h0, c0, whh_if, whh_go,
                    bias_if, bias_go, cb0, cb1, blv, clv,
                    pos_out, lv_out, hT_out, cT_out);
    } else {
        run_lstm<3>(&sm, N4BLK * 4 + (b - N4BLK) * 3, lane, x, h0, c0, whh_if, whh_go,
                    bias_if, bias_go, cb0, cb1, blv, clv,
                    pos_out, lv_out, hT_out, cT_out);
    }
}

extern "C" void kernel_launch(void* const* d_in, const int* in_sizes, int n_in,
                              void* d_out, int out_size)
{
    const float* x    = (const float*)d_in[0];
    const float* h0   = (const float*)d_in[1];
    const float* c0   = (const float*)d_in[2];
    const float* W_ih = (const float*)d_in[3];
    const float* W_hh = (const float*)d_in[4];
    const float* b_ih = (const float*)d_in[5];
    const float* b_hh = (const float*)d_in[6];
    const float* W_all= (const float*)d_in[7];
    const float* b_all= (const float*)d_in[8];
    const float* W_pos= (const float*)d_in[9];
    const float* b_pos= (const float*)d_in[10];
    const float* W_lv = (const float*)d_in[11];
    const float* b_lv = (const float*)d_in[12];
    float* out = (float*)d_out;

    lstm_fused_kernel<<<GRIDB, 32>>>(x, h0, c0, W_ih, W_hh, b_ih, b_hh,
                                     W_all, b_all, W_pos, b_pos, W_lv, b_lv, out);
}

// round 5
// speedup vs baseline: 1.0434x; 1.0434x over previous
#include <cuda_runtime.h>

#define HIDDEN 32
#define FEAT 30
#define TSTEPS 512
#define BATCH 4096
#define CHUNK 16
#define FULLMASK 0xffffffffu

typedef unsigned long long ull;

__device__ __forceinline__ float tanhap(float x) {
    float y; asm("tanh.approx.f32 %0, %1;" : "=f"(y) : "f"(x)); return y;
}
__device__ __forceinline__ float sigf(float x) {
    return fmaf(0.5f, tanhap(0.5f * x), 0.5f);
}
__device__ __forceinline__ ull fma2(ull a, ull b, ull c) {
    ull d;
    asm("fma.rn.f32x2 %0, %1, %2, %3;" : "=l"(d) : "l"(a), "l"(b), "l"(c));
    return d;
}
__device__ __forceinline__ ull pack2(float lo, float hi) {
    ull d; asm("mov.b64 %0, {%1, %2};" : "=l"(d) : "f"(lo), "f"(hi)); return d;
}
__device__ __forceinline__ ull dup2(float v) {
    ull d; asm("mov.b64 %0, {%1, %1};" : "=l"(d) : "f"(v)); return d;
}
__device__ __forceinline__ float2 unpack2(ull v) {
    float lo, hi; asm("mov.b64 {%0, %1}, %2;" : "=f"(lo), "=f"(hi) : "l"(v));
    return make_float2(lo, hi);
}

struct Smem {
    ulonglong2 sWih[FEAT][HIDDEN];   // [k][j] = ((w_i,w_f),(w_g,w_o))
    ulonglong2 xq[2][HIDDEN];        // [buf][k] = ((xA,xB),(xC,xD))  (k<30 used)
    ulonglong2 hq[2][HIDDEN];        // [buf][j] = ((hA,hB),(hC,hD))
    ulonglong2 hist[CHUNK][33];      // [slot][j] = masked h, padded
    ull wcd0[HIDDEN], wcd1[HIDDEN], wcdl[HIDDEN];
};

__global__ void __launch_bounds__(32)
lstm_fused_kernel(
    const float* __restrict__ x, const float* __restrict__ h0, const float* __restrict__ c0,
    const float* __restrict__ W_ih, const float* __restrict__ W_hh,
    const float* __restrict__ b_ih, const float* __restrict__ b_hh,
    const float* __restrict__ W_all, const float* __restrict__ b_all,
    const float* __restrict__ W_pos, const float* __restrict__ b_pos,
    const float* __restrict__ W_lv, const float* __restrict__ b_lv,
    float* __restrict__ out)
{
    __shared__ Smem sm;
    const int lane = threadIdx.x;
    const int s0 = blockIdx.x * 4;

    // ---- one-time init ----
    #pragma unroll
    for (int k = 0; k < FEAT; ++k) {
        sm.sWih[k][lane] = make_ulonglong2(
            pack2(W_ih[lane * FEAT + k],        W_ih[(32 + lane) * FEAT + k]),
            pack2(W_ih[(64 + lane) * FEAT + k], W_ih[(96 + lane) * FEAT + k]));
    }
    ull whh_if[HIDDEN], whh_go[HIDDEN];
    #pragma unroll
    for (int k = 0; k < HIDDEN; ++k) {
        whh_if[k] = pack2(W_hh[lane * HIDDEN + k],        W_hh[(32 + lane) * HIDDEN + k]);
        whh_go[k] = pack2(W_hh[(64 + lane) * HIDDEN + k], W_hh[(96 + lane) * HIDDEN + k]);
    }
    // folded heads: wc = W_pos @ W_all, cb = W_pos @ b_all + b_pos
    float wc0 = 0.f, wc1 = 0.f, cb0 = b_pos[0], cb1 = b_pos[1];
    #pragma unroll
    for (int m = 0; m < HIDDEN; ++m) {
        const float wa = W_all[m * HIDDEN + lane];
        wc0 = fmaf(W_pos[m],      wa, wc0);
        wc1 = fmaf(W_pos[32 + m], wa, wc1);
        cb0 = fmaf(W_pos[m],      b_all[m], cb0);
        cb1 = fmaf(W_pos[32 + m], b_all[m], cb1);
    }
    sm.wcd0[lane] = dup2(wc0);
    sm.wcd1[lane] = dup2(wc1);
    sm.wcdl[lane] = dup2(W_lv[lane]);
    const float blv = b_lv[0];

    const ull bias_if = pack2(b_ih[lane]      + b_hh[lane],
                              b_ih[32 + lane] + b_hh[32 + lane]);
    const ull bias_go = pack2(b_ih[64 + lane] + b_hh[64 + lane],
                              b_ih[96 + lane] + b_hh[96 + lane]);

    const float* xA = x + (size_t)(s0 + 0) * TSTEPS * FEAT;
    const float* xB = x + (size_t)(s0 + 1) * TSTEPS * FEAT;
    const float* xC = x + (size_t)(s0 + 2) * TSTEPS * FEAT;
    const float* xD = x + (size_t)(s0 + 3) * TSTEPS * FEAT;

    float hA = h0[(s0 + 0) * HIDDEN + lane], cA = c0[(s0 + 0) * HIDDEN + lane];
    float hB = h0[(s0 + 1) * HIDDEN + lane], cB = c0[(s0 + 1) * HIDDEN + lane];
    float hC = h0[(s0 + 2) * HIDDEN + lane], cC = c0[(s0 + 2) * HIDDEN + lane];
    float hD = h0[(s0 + 3) * HIDDEN + lane], cD = c0[(s0 + 3) * HIDDEN + lane];

    sm.hq[0][lane] = make_ulonglong2(pack2(hA, hB), pack2(hC, hD));
    // Unconditional: lanes 30/31 fill unused slots with adjacent-row data (never read).
    sm.xq[0][lane] = make_ulonglong2(pack2(xA[lane], xB[lane]), pack2(xC[lane], xD[lane]));
    __syncwarp();

    float* pos_out = out;                                   // [B,T,2]
    float* lv_out  = out + (size_t)BATCH * TSTEPS * 2;      // [B,T,1]
    float* hT_out  = out + (size_t)BATCH * TSTEPS * 3;      // [1,B,H]
    float* cT_out  = hT_out + BATCH * HIDDEN;               // [1,B,H]

    for (int t = 0; t < TSTEPS; ++t) {
        const int bsel = t & 1;
        const int slot = t & (CHUNK - 1);

        // Unconditional prefetch (clamped at the tail; always in-bounds).
        const int tn = (t + 1 < TSTEPS) ? (t + 1) : t;
        const int o = tn * FEAT + lane;
        const float xnA = xA[o], xnB = xB[o], xnC = xC[o], xnD = xD[o];

        const ulonglong2 mq = sm.xq[bsel][FEAT - 1];
        const float2 mAB = unpack2(mq.x), mCD = unpack2(mq.y);
        const bool aA = (mAB.x == 1.0f), aB = (mAB.y == 1.0f);
        const bool aC = (mCD.x == 1.0f), aD = (mCD.y == 1.0f);

        ull ifA = bias_if, goA = bias_go, ifB = bias_if, goB = bias_go;
        ull ifC = bias_if, goC = bias_go, ifD = bias_if, goD = bias_go;
        #pragma unroll
        for (int k = 0; k < FEAT; ++k) {
            const ulonglong2 xk = sm.xq[bsel][k];
            const float2 uab = unpack2(xk.x), ucd = unpack2(xk.y);
            const ulonglong2 w = sm.sWih[k][lane];
            const ull vA = dup2(uab.x), vB = dup2(uab.y);
            const ull vC = dup2(ucd.x), vD = dup2(ucd.y);
            ifA = fma2(vA, w.x, ifA); goA = fma2(vA, w.y, goA);
            ifB = fma2(vB, w.x, ifB); goB = fma2(vB, w.y, goB);
            ifC = fma2(vC, w.x, ifC); goC = fma2(vC, w.y, goC);
            ifD = fma2(vD, w.x, ifD); goD = fma2(vD, w.y, goD);
        }
        #pragma unroll
        for (int k = 0; k < HIDDEN; ++k) {
            const ulonglong2 hk = sm.hq[bsel][k];
            const float2 uab = unpack2(hk.x), ucd = unpack2(hk.y);
            const ull wi = whh_if[k], wg = whh_go[k];
            const ull vA = dup2(uab.x), vB = dup2(uab.y);
            const ull vC = dup2(ucd.x), vD = dup2(ucd.y);
            ifA = fma2(vA, wi, ifA); goA = fma2(vA, wg, goA);
            ifB = fma2(vB, wi, ifB); goB = fma2(vB, wg, goB);
            ifC = fma2(vC, wi, ifC); goC = fma2(vC, wg, goC);
            ifD = fma2(vD, wi, ifD); goD = fma2(vD, wg, goD);
        }

        float hsA, hsB, hsC, hsD;
        {
            const float2 g1 = unpack2(ifA), g2 = unpack2(goA);
            const float cn = fmaf(sigf(g1.y), cA, sigf(g1.x) * tanhap(g2.x));
            const float hn = sigf(g2.y) * tanhap(cn);
            cA = aA ? cn : cA; hA = aA ? hn : hA; hsA = aA ? hn : 0.f;
        }
        {
            const float2 g1 = unpack2(ifB), g2 = unpack2(goB);
            const float cn = fmaf(sigf(g1.y), cB, sigf(g1.x) * tanhap(g2.x));
            const float hn = sigf(g2.y) * tanhap(cn);
            cB = aB ? cn : cB; hB = aB ? hn : hB; hsB = aB ? hn : 0.f;
        }
        {
            const float2 g1 = unpack2(ifC), g2 = unpack2(goC);
            const float cn = fmaf(sigf(g1.y), cC, sigf(g1.x) * tanhap(g2.x));
            const float hn = sigf(g2.y) * tanhap(cn);
            cC = aC ? cn : cC; hC = aC ? hn : hC; hsC = aC ? hn : 0.f;
        }
        {
            const float2 g1 = unpack2(ifD), g2 = unpack2(goD);
            const float cn = fmaf(sigf(g1.y), cD, sigf(g1.x) * tanhap(g2.x));
            const float hn = sigf(g2.y) * tanhap(cn);
            cD = aD ? cn : cD; hD = aD ? hn : hD; hsD = aD ? hn : 0.f;
        }

        sm.hq[bsel ^ 1][lane] = make_ulonglong2(pack2(hA, hB), pack2(hC, hD));
        sm.hist[slot][lane]   = make_ulonglong2(pack2(hsA, hsB), pack2(hsC, hsD));
        sm.xq[bsel ^ 1][lane] = make_ulonglong2(pack2(xnA, xnB), pack2(xnC, xnD));
        __syncwarp();

        // bulk head phase over the finished 16-step chunk
        if (slot == CHUNK - 1) {
            const int tt = lane & 15;
            const int pr = lane >> 4;
            const ull* hrow = reinterpret_cast<const ull*>(&sm.hist[tt][0]) + pr;
            ull p0 = 0ULL, p1 = 0ULL, pl = 0ULL;
            #pragma unroll
            for (int j = 0; j < HIDDEN; ++j) {
                const ull hv = hrow[j * 2];
                p0 = fma2(hv, sm.wcd0[j], p0);
                p1 = fma2(hv, sm.wcd1[j], p1);
                pl = fma2(hv, sm.wcdl[j], pl);
            }
            const float2 q0 = unpack2(p0), q1 = unpack2(p1), ql = unpack2(pl);
            const int tg = t - (CHUNK - 1) + tt;
            const size_t oA = (size_t)(s0 + pr * 2) * TSTEPS + tg;
            const size_t oB = oA + TSTEPS;
            reinterpret_cast<float2*>(pos_out)[oA] = make_float2(q0.x + cb0, q1.x + cb1);
            reinterpret_cast<float2*>(pos_out)[oB] = make_float2(q0.y + cb0, q1.y + cb1);
            lv_out[oA] = sigf(ql.x + blv);
            lv_out[oB] = sigf(ql.y + blv);
            __syncwarp();
        }
    }

    hT_out[(s0 + 0) * HIDDEN + lane] = hA;
    hT_out[(s0 + 1) * HIDDEN + lane] = hB;
    hT_out[(s0 + 2) * HIDDEN + lane] = hC;
    hT_out[(s0 + 3) * HIDDEN + lane] = hD;
    cT_out[(s0 + 0) * HIDDEN + lane] = cA;
    cT_out[(s0 + 1) * HIDDEN + lane] = cB;
    cT_out[(s0 + 2) * HIDDEN + lane] = cC;
    cT_out[(s0 + 3) * HIDDEN + lane] = cD;
}

extern "C" void kernel_launch(void* const* d_in, const int* in_sizes, int n_in,
                              void* d_out, int out_size)
{
    const float* x    = (const float*)d_in[0];
    const float* h0   = (const float*)d_in[1];
    const float* c0   = (const float*)d_in[2];
    const float* W_ih = (const float*)d_in[3];
    const float* W_hh = (const float*)d_in[4];
    const float* b_ih = (const float*)d_in[5];
    const float* b_hh = (const float*)d_in[6];
    const float* W_all= (const float*)d_in[7];
    const float* b_all= (const float*)d_in[8];
    const float* W_pos= (const float*)d_in[9];
    const float* b_pos= (const float*)d_in[10];
    const float* W_lv = (const float*)d_in[11];
    const float* b_lv = (const float*)d_in[12];
    float* out = (float*)d_out;

    lstm_fused_kernel<<<BATCH / 4, 32>>>(x, h0, c0, W_ih, W_hh, b_ih, b_hh,
                                         W_all, b_all, W_pos, b_pos, W_lv, b_lv, out);
}